// round 12
// baseline (speedup 1.0000x reference)
#include <cuda_runtime.h>
#include <cuda_bf16.h>
#include <math.h>
#include <stdint.h>

#define NTOK 1024
#define HID  2048
#define NH   16
#define HD   128
#define QKVD 6144
#define FFN  2048
#define NEXP 8
#define TK   2
#define BLK  256
#define NBLK 4

// ---------------- scratch (static device globals; no allocs) ----------------
__device__ float g_h[NTOK*HID];
__device__ float g_qkv[NTOK*QKVD];
__device__ float g_gate[NTOK*HID];
__device__ float g_attn[NTOK*HID];
__device__ float g_attnng[NTOK*HID];
__device__ float g_hid2[NTOK*HID];
__device__ float g_h2[NTOK*HID];
__device__ float g_kvC[2*NH*NBLK*HD*HD];   // two row-half partials
__device__ float g_kvin[NH*NBLK*HD*HD];
__device__ float g_act[NTOK*TK*FFN];       // silu(h2@w1) per slot
__device__ float g_act2[NTOK*TK*FFN];      // h2@w3 per slot
__device__ float g_yslot[NTOK*TK*HID];
__device__ float g_slotw[NTOK*TK];
__device__ int   g_btok[NEXP*NTOK];
__device__ int   g_bdst[NEXP*NTOK];
__device__ int   g_cnt[NEXP];

// ---------------- mma.sync bf16 + ldmatrix ----------------
__device__ __forceinline__ void mma_bf16(float* c,
    uint32_t a0, uint32_t a1, uint32_t a2, uint32_t a3, uint32_t b0, uint32_t b1)
{
    asm volatile(
        "mma.sync.aligned.m16n8k16.row.col.f32.bf16.bf16.f32 "
        "{%0,%1,%2,%3}, {%4,%5,%6,%7}, {%8,%9}, {%0,%1,%2,%3};"
        : "+f"(c[0]), "+f"(c[1]), "+f"(c[2]), "+f"(c[3])
        : "r"(a0), "r"(a1), "r"(a2), "r"(a3), "r"(b0), "r"(b1));
}

__device__ __forceinline__ void ldsm4(uint32_t* r, uint32_t addr)
{
    asm volatile("ldmatrix.sync.aligned.m8n8.x4.shared.b16 {%0,%1,%2,%3}, [%4];"
        : "=r"(r[0]), "=r"(r[1]), "=r"(r[2]), "=r"(r[3]) : "r"(addr));
}

__device__ __forceinline__ uint32_t smem_u32(const void* p) {
    uint32_t a;
    asm("{ .reg .u64 t; cvta.to.shared.u64 t, %1; cvt.u32.u64 %0, t; }" : "=r"(a) : "l"(p));
    return a;
}

// fp32 pair -> bf16x2 hi + bf16x2 lo (residual); x in low half, y in high half
__device__ __forceinline__ void cvt_split(float x, float y, uint32_t& hi, uint32_t& lo)
{
    asm("cvt.rn.satfinite.bf16x2.f32 %0, %1, %2;" : "=r"(hi) : "f"(y), "f"(x));
    float hx = __uint_as_float(hi << 16);
    float hy = __uint_as_float(hi & 0xFFFF0000u);
    float lx = x - hx, ly = y - hy;
    asm("cvt.rn.satfinite.bf16x2.f32 %0, %1, %2;" : "=r"(lo) : "f"(ly), "f"(lx));
}

// ---------------- split-bf16 tensor GEMM core: C[.,N] = epi(A@B^T) ------------
// CTA tile 128x128, 8 warps (4 M x 2 N), warp tile 32x64, K chunks of 32.
// smem tiles Ahi/Alo/Bhi/Blo: 128 rows x 32 bf16, pitch 40 bf16; double buffered.
#define KC      32
#define PITCHW  20
#define TILEW   (128*PITCHW)
#define BUFW    (4*TILEW)
#define BG_SMEM (2*BUFW*4)

// epi: 0 none, 1 silu, 2 sigmoid, 3 +Res
__device__ __forceinline__ void gemm_cta(
    const float* __restrict__ A, const float* __restrict__ A2,
    const float* __restrict__ B,
    const float* __restrict__ Res, float* __restrict__ C,
    int N, int K, int bm, int bn, int mrows,
    const int* __restrict__ gat, const int* __restrict__ sca, int epi)
{
    extern __shared__ uint32_t smw[];
    uint32_t sbase = smem_u32(smw);

    int tid = threadIdx.x, wid = tid >> 5, lane = tid & 31;
    int wm = wid & 3, wn = wid >> 2;
    int mrow = lane & 7, mat = lane >> 3;
    uint32_t aoff[2], boff[4];
    #pragma unroll
    for (int i = 0; i < 2; i++)
        aoff[i] = (uint32_t)(((wm*32 + i*16 + ((mat & 1) << 3) + mrow)*PITCHW
                              + ((mat >> 1) << 2)) * 4);
    #pragma unroll
    for (int g = 0; g < 4; g++)
        boff[g] = (uint32_t)(((wn*64 + (2*g + (mat >> 1))*8 + mrow)*PITCHW
                              + ((mat & 1) << 2)) * 4);

    int lrow = tid >> 1, half = tid & 1;
    int ar = bm + lrow; if (ar >= mrows) ar = mrows - 1;
    int arix = gat ? gat[ar] : ar;
    const float* Arow  = A + (size_t)arix*K + half*16;
    const float* A2row = A2 ? A2 + (size_t)arix*K + half*16 : nullptr;
    const float* Brow  = B + (size_t)(bn + lrow)*K + half*16;

    float acc[2][8][4];
    #pragma unroll
    for (int i = 0; i < 2; i++)
        #pragma unroll
        for (int j = 0; j < 8; j++)
            #pragma unroll
            for (int q = 0; q < 4; q++) acc[i][j][q] = 0.f;

    float4 pa[4], pb[4];
    auto prefetch = [&](int t) {
        const float* Ap = Arow + t*KC;
        const float* Bp = Brow + t*KC;
        #pragma unroll
        for (int j = 0; j < 4; j++) {
            pa[j] = *(const float4*)(Ap + j*4);
            pb[j] = *(const float4*)(Bp + j*4);
        }
        if (A2row) {
            const float* Mp = A2row + t*KC;
            #pragma unroll
            for (int j = 0; j < 4; j++) {
                float4 m = *(const float4*)(Mp + j*4);
                pa[j].x *= m.x; pa[j].y *= m.y; pa[j].z *= m.z; pa[j].w *= m.w;
            }
        }
    };

    int ntiles = K / KC;
    int swbase = lrow*PITCHW + half*8;

    auto store_tiles = [&](int buf) {
        uint32_t* Ah = smw + buf*BUFW;
        uint32_t* Al = Ah + TILEW;
        uint32_t* Bh = Al + TILEW;
        uint32_t* Bl = Bh + TILEW;
        #pragma unroll
        for (int j = 0; j < 4; j++) {
            uint32_t h0, l0, h1, l1;
            int o = swbase + j*2;
            cvt_split(pa[j].x, pa[j].y, h0, l0);
            cvt_split(pa[j].z, pa[j].w, h1, l1);
            *(uint2*)(Ah + o) = make_uint2(h0, h1);
            *(uint2*)(Al + o) = make_uint2(l0, l1);
            cvt_split(pb[j].x, pb[j].y, h0, l0);
            cvt_split(pb[j].z, pb[j].w, h1, l1);
            *(uint2*)(Bh + o) = make_uint2(h0, h1);
            *(uint2*)(Bl + o) = make_uint2(l0, l1);
        }
    };

    prefetch(0);
    store_tiles(0);
    __syncthreads();

    for (int t = 0; t < ntiles; t++) {
        int buf = t & 1;
        if (t + 1 < ntiles) prefetch(t + 1);

        uint32_t bAh = sbase + (uint32_t)(buf*BUFW*4);
        uint32_t bAl = bAh + TILEW*4;
        uint32_t bBh = bAl + TILEW*4;
        uint32_t bBl = bBh + TILEW*4;

        #pragma unroll
        for (int ks = 0; ks < 2; ks++) {
            uint32_t ks32 = (uint32_t)(ks*32);
            uint32_t ah[2][4], al[2][4], bh[4][4], bl[4][4];
            #pragma unroll
            for (int i = 0; i < 2; i++) {
                ldsm4(ah[i], bAh + aoff[i] + ks32);
                ldsm4(al[i], bAl + aoff[i] + ks32);
            }
            #pragma unroll
            for (int g = 0; g < 4; g++) {
                ldsm4(bh[g], bBh + boff[g] + ks32);
                ldsm4(bl[g], bBl + boff[g] + ks32);
            }
            #pragma unroll
            for (int i = 0; i < 2; i++)
                #pragma unroll
                for (int j = 0; j < 8; j++) {
                    int g = j >> 1, o = (j & 1)*2;
                    mma_bf16(acc[i][j], ah[i][0], ah[i][1], ah[i][2], ah[i][3], bh[g][o], bh[g][o+1]);
                    mma_bf16(acc[i][j], ah[i][0], ah[i][1], ah[i][2], ah[i][3], bl[g][o], bl[g][o+1]);
                    mma_bf16(acc[i][j], al[i][0], al[i][1], al[i][2], al[i][3], bh[g][o], bh[g][o+1]);
                }
        }
        if (t + 1 < ntiles) store_tiles(buf ^ 1);
        __syncthreads();
    }

    // epilogue
    int etq = lane >> 2, etr = lane & 3;
    #pragma unroll
    for (int i = 0; i < 2; i++) {
        #pragma unroll
        for (int half8 = 0; half8 < 2; half8++) {
            int gm = bm + wm*32 + i*16 + half8*8 + etq;
            if (gm < mrows) {
                int orow = sca ? sca[gm] : gm;
                #pragma unroll
                for (int j = 0; j < 8; j++) {
                    int col = bn + wn*64 + j*8 + etr*2;
                    float vx = acc[i][j][half8*2 + 0];
                    float vy = acc[i][j][half8*2 + 1];
                    float* cp = C + (size_t)orow*N + col;
                    if (epi == 1) {
                        vx = vx/(1.f + __expf(-vx)); vy = vy/(1.f + __expf(-vy));
                    } else if (epi == 2) {
                        vx = 1.f/(1.f + __expf(-vx)); vy = 1.f/(1.f + __expf(-vy));
                    } else if (epi == 3) {
                        const float* rp = Res + (size_t)gm*N + col;
                        vx += rp[0]; vy += rp[1];
                    }
                    cp[0] = vx; cp[1] = vy;
                }
            }
        }
    }
}

// dense GEMM, runtime epilogue
__global__ void __launch_bounds__(256) bgemm_std_kernel(
    const float* __restrict__ A, const float* __restrict__ B,
    const float* __restrict__ Res, float* __restrict__ C,
    int M, int N, int K, int epi)
{
    gemm_cta(A, nullptr, B, Res, C, N, K, blockIdx.y*128, blockIdx.x*128, M,
             nullptr, nullptr, epi);
}

// fused qkv (silu) + gate (sigmoid): one launch, both read A
__global__ void __launch_bounds__(256) bgemm_qkvgate_kernel(
    const float* __restrict__ A, const float* __restrict__ Bq,
    const float* __restrict__ Bg, float* __restrict__ Cq, float* __restrict__ Cg)
{
    int bx = blockIdx.x;
    const float* B; float* C; int N, bn, epi;
    if (bx < QKVD/128) { B = Bq; C = Cq; N = QKVD; bn = bx*128; epi = 1; }
    else               { B = Bg; C = Cg; N = HID;  bn = (bx - QKVD/128)*128; epi = 2; }
    gemm_cta(A, nullptr, B, nullptr, C, N, HID, blockIdx.y*128, bn, NTOK,
             nullptr, nullptr, epi);
}

// fused MoE stage1+stage2: z<8 -> w1/silu->act ; z>=8 -> w3/none->act2
__global__ void __launch_bounds__(256) moe_s12_kernel(
    const float* __restrict__ A, const float* __restrict__ w1,
    const float* __restrict__ w3, float* __restrict__ act, float* __restrict__ act2,
    const int* __restrict__ btok, const int* __restrict__ bdst,
    const int* __restrict__ cnt)
{
    int z = blockIdx.z, e = z & 7;
    int mrows = cnt[e];
    int bm = blockIdx.y*128;
    if (bm >= mrows) return;
    const float* B = (z < 8 ? w1 : w3) + (size_t)e*FFN*HID;
    float* C = (z < 8) ? act : act2;
    int epi = (z < 8) ? 1 : 0;
    gemm_cta(A, nullptr, B, nullptr, C, FFN, HID, bm, blockIdx.x*128, mrows,
             btok + e*NTOK, bdst + e*NTOK, epi);
}

// MoE stage3: A = act (*) act2 (elementwise in loader), B = w2
__global__ void __launch_bounds__(256) moe_s3_kernel(
    const float* __restrict__ act, const float* __restrict__ act2,
    const float* __restrict__ w2, float* __restrict__ yslot,
    const int* __restrict__ bdst, const int* __restrict__ cnt)
{
    int e = blockIdx.z;
    int mrows = cnt[e];
    int bm = blockIdx.y*128;
    if (bm >= mrows) return;
    gemm_cta(act, act2, w2 + (size_t)e*HID*FFN, nullptr, yslot, HID, FFN,
             bm, blockIdx.x*128, mrows, bdst + e*NTOK, bdst + e*NTOK, 0);
}

// ---------------- rmsnorm ----------------
__global__ void rmsnorm_kernel(const float* __restrict__ in, const float* __restrict__ w,
                               float* __restrict__ out, float eps)
{
    int n = blockIdx.x; int tid = threadIdx.x;
    const float* row = in + (size_t)n*HID;
    float s = 0.f;
    for (int c = tid; c < HID; c += 256) { float v = row[c]; s += v*v; }
    __shared__ float red[256];
    red[tid] = s; __syncthreads();
    for (int o = 128; o > 0; o >>= 1) { if (tid < o) red[tid] += red[tid+o]; __syncthreads(); }
    float inv = rsqrtf(red[0]/(float)HID + eps);
    float* orow = out + (size_t)n*HID;
    for (int c = tid; c < HID; c += 256) orow[c] = row[c]*inv*w[c];
}

__global__ void rmsnorm_gate_kernel(const float* __restrict__ in, const float* __restrict__ w,
                                    const float* __restrict__ gate, float* __restrict__ out)
{
    int n = blockIdx.x; int tid = threadIdx.x;
    const float* row = in + (size_t)n*HID;
    float s = 0.f;
    for (int c = tid; c < HID; c += 256) { float v = row[c]; s += v*v; }
    __shared__ float red[256];
    red[tid] = s; __syncthreads();
    for (int o = 128; o > 0; o >>= 1) { if (tid < o) red[tid] += red[tid+o]; __syncthreads(); }
    float inv = rsqrtf(red[0]/(float)HID + 1.1920929e-07f);
    const float* grow = gate + (size_t)n*HID;
    float* orow = out + (size_t)n*HID;
    for (int c = tid; c < HID; c += 256) orow[c] = row[c]*inv*w[c]*grow[c];
}

// ---------------- router + routing ----------------
__global__ void zero_cnt_kernel(int* cnt) { if (threadIdx.x < NEXP) cnt[threadIdx.x] = 0; }

__global__ void router_kernel(const float* __restrict__ h2, const float* __restrict__ rw,
                              float* __restrict__ slotw, int* __restrict__ btok,
                              int* __restrict__ bdst, int* __restrict__ cnt)
{
    int n = blockIdx.x; int tid = threadIdx.x;
    int e = tid >> 5, lane = tid & 31;
    const float* xr = h2 + (size_t)n*HID;
    const float* wr = rw + (size_t)e*HID;
    float s = 0.f;
    for (int k = lane; k < HID; k += 32) s += xr[k]*wr[k];
    for (int o = 16; o > 0; o >>= 1) s += __shfl_down_sync(0xffffffffu, s, o);
    __shared__ float lg[NEXP];
    if (lane == 0) lg[e] = s;
    __syncthreads();
    if (tid == 0) {
        float m = lg[0];
        for (int i = 1; i < NEXP; i++) m = fmaxf(m, lg[i]);
        float p[NEXP];
        for (int i = 0; i < NEXP; i++) p[i] = expf(lg[i]-m);
        int i0 = 0;
        for (int i = 1; i < NEXP; i++) if (p[i] > p[i0]) i0 = i;
        int i1 = (i0 == 0) ? 1 : 0;
        for (int i = 0; i < NEXP; i++) if (i != i0 && p[i] > p[i1]) i1 = i;
        float inv = 1.f/(p[i0]+p[i1]);
        slotw[n*2]   = p[i0]*inv;
        slotw[n*2+1] = p[i1]*inv;
        int pos0 = atomicAdd(&cnt[i0], 1); btok[i0*NTOK+pos0] = n; bdst[i0*NTOK+pos0] = n*2;
        int pos1 = atomicAdd(&cnt[i1], 1); btok[i1*NTOK+pos1] = n; bdst[i1*NTOK+pos1] = n*2+1;
    }
}

// ---------------- attention: per-block KV contribution (2 row-half partials) --
__global__ void __launch_bounds__(256) kv_contrib_kernel(const float* __restrict__ slope)
{
    int blk = blockIdx.x, h = blockIdx.y, part = blockIdx.z;
    float sl = slope[h];
    __shared__ float Ks[32][132];
    __shared__ float Vs[32][132];
    int tid = threadIdx.x, ty = tid >> 4, tx = tid & 15;
    int lrow = tid >> 3, cb = tid & 7;

    float acc[8][8];
    #pragma unroll
    for (int i = 0; i < 8; i++)
        #pragma unroll
        for (int j = 0; j < 8; j++) acc[i][j] = 0.f;

    for (int i0 = 0; i0 < 128; i0 += 32) {
        int rowin = part*128 + i0 + lrow;
        int gi = blk*BLK + rowin;
        float kd = __expf(-sl*(float)(BLK - (rowin + 1)));
        const float* kp = g_qkv + (size_t)gi*QKVD + h*384 + 128;
        #pragma unroll
        for (int j = 0; j < 4; j++) {
            int c = (cb + j*8)*4;
            float4 kv = *(const float4*)(kp + c);
            Ks[lrow][c+0] = kv.x*kd; Ks[lrow][c+1] = kv.y*kd;
            Ks[lrow][c+2] = kv.z*kd; Ks[lrow][c+3] = kv.w*kd;
            float4 vv = *(const float4*)(kp + 128 + c);
            *(float4*)&Vs[lrow][c] = vv;
        }
        __syncthreads();
        #pragma unroll
        for (int i = 0; i < 32; i++) {
            float4 a0 = *(const float4*)&Ks[i][ty*8];
            float4 a1 = *(const float4*)&Ks[i][ty*8+4];
            float4 b0 = *(const float4*)&Vs[i][tx*8];
            float4 b1 = *(const float4*)&Vs[i][tx*8+4];
            float a[8] = {a0.x,a0.y,a0.z,a0.w,a1.x,a1.y,a1.z,a1.w};
            float b[8] = {b0.x,b0.y,b0.z,b0.w,b1.x,b1.y,b1.z,b1.w};
            #pragma unroll
            for (int rr = 0; rr < 8; rr++)
                #pragma unroll
                for (int cc = 0; cc < 8; cc++) acc[rr][cc] += a[rr]*b[cc];
        }
        __syncthreads();
    }
    float* cp = g_kvC + (size_t)((part*NH + h)*NBLK + blk)*HD*HD;
    #pragma unroll
    for (int rr = 0; rr < 8; rr++)
        #pragma unroll
        for (int cc = 0; cc < 8; cc++)
            cp[(size_t)(ty*8+rr)*HD + tx*8 + cc] = acc[rr][cc];
}

// kv_in(i) = sum_{j<i} bdecay^{i-1-j} (C0_j + C1_j)
__global__ void kv_prefix_kernel(const float* __restrict__ slope)
{
    int i = blockIdx.x, h = blockIdx.y, tid = threadIdx.x;
    float bd = __expf(-slope[h]*(float)BLK);
    const float* b0 = g_kvC + (size_t)(h*NBLK)*HD*HD;
    const float* b1 = g_kvC + (size_t)((NH + h)*NBLK)*HD*HD;
    float* outp = g_kvin + (size_t)(h*NBLK + i)*HD*HD;
    for (int x = tid; x < HD*HD; x += 256) {
        float s = 0.f, w = 1.f;
        for (int j = i-1; j >= 0; j--) {
            float cj = b0[(size_t)j*HD*HD + x] + b1[(size_t)j*HD*HD + x];
            s += w*cj; w *= bd;
        }
        outp[x] = s;
    }
}

#define ATTN_SMEM ((128*132 + 128*36 + 32*132 + 32*132)*4)
__global__ void __launch_bounds__(256) attn_out_kernel(const float* __restrict__ slope)
{
    int m0 = blockIdx.x*128;
    int blk = blockIdx.y;
    int h = blockIdx.z;
    float sl = slope[h];

    extern __shared__ float sm[];
    float* QsT = sm;
    float* KsT = QsT + 128*132;
    float* Vs  = KsT + 128*36;
    float* ScT = Vs  + 32*132;

    int tid = threadIdx.x, ty = tid >> 4, tx = tid & 15;

    {
        int m = tid >> 1, half = tid & 1;
        const float* qp = g_qkv + (size_t)(blk*BLK + m0 + m)*QKVD + h*384;
        #pragma unroll
        for (int j = 0; j < 16; j++) {
            int d = (half*16 + j)*4;
            float4 q = *(const float4*)(qp + d);
            QsT[(d+0)*132 + m] = q.x; QsT[(d+1)*132 + m] = q.y;
            QsT[(d+2)*132 + m] = q.z; QsT[(d+3)*132 + m] = q.w;
        }
    }
    float qd[8];
    #pragma unroll
    for (int i = 0; i < 8; i++) qd[i] = __expf(-sl*(float)(m0 + ty*8 + i + 1));

    float acc[8][8];
    #pragma unroll
    for (int i = 0; i < 8; i++)
        #pragma unroll
        for (int j = 0; j < 8; j++) acc[i][j] = 0.f;
    __syncthreads();

    int lrow = tid >> 3, cb = tid & 7;

    const float* kvp = g_kvin + (size_t)(h*NBLK + blk)*HD*HD;
    for (int dc = 0; dc < 4; dc++) {
        #pragma unroll
        for (int j = 0; j < 4; j++) {
            int c = (cb + j*8)*4;
            float4 v = *(const float4*)(kvp + (size_t)(dc*32 + lrow)*HD + c);
            *(float4*)&Vs[lrow*132 + c] = v;
        }
        __syncthreads();
        #pragma unroll
        for (int i = 0; i < 32; i++) {
            int d = dc*32 + i;
            float4 a0 = *(const float4*)&QsT[d*132 + ty*8];
            float4 a1 = *(const float4*)&QsT[d*132 + ty*8 + 4];
            float4 b0 = *(const float4*)&Vs[i*132 + tx*8];
            float4 b1 = *(const float4*)&Vs[i*132 + tx*8 + 4];
            float a[8] = {a0.x,a0.y,a0.z,a0.w,a1.x,a1.y,a1.z,a1.w};
            float b[8] = {b0.x,b0.y,b0.z,b0.w,b1.x,b1.y,b1.z,b1.w};
            #pragma unroll
            for (int rr = 0; rr < 8; rr++) {
                float av = a[rr]*qd[rr];
                #pragma unroll
                for (int cc = 0; cc < 8; cc++) acc[rr][cc] += av*b[cc];
            }
        }
        __syncthreads();
    }

    int ncmax = (m0 + 128)/32;
    for (int nc = 0; nc < ncmax; nc++) {
        int n0 = nc*32;
        const float* kp = g_qkv + (size_t)(blk*BLK + n0 + lrow)*QKVD + h*384 + 128;
        #pragma unroll
        for (int j = 0; j < 4; j++) {
            int d = (cb + j*8)*4;
            float4 kv = *(const float4*)(kp + d);
            KsT[(d+0)*36 + lrow] = kv.x; KsT[(d+1)*36 + lrow] = kv.y;
            KsT[(d+2)*36 + lrow] = kv.z; KsT[(d+3)*36 + lrow] = kv.w;
            float4 vv = *(const float4*)(kp + 128 + d);
            *(float4*)&Vs[lrow*132 + d] = vv;
        }
        __syncthreads();

        float s[8][2];
        #pragma unroll
        for (int rr = 0; rr < 8; rr++) { s[rr][0] = 0.f; s[rr][1] = 0.f; }
        for (int d = 0; d < 128; d++) {
            float4 a0 = *(const float4*)&QsT[d*132 + ty*8];
            float4 a1 = *(const float4*)&QsT[d*132 + ty*8 + 4];
            float b0 = KsT[d*36 + tx*2], b1 = KsT[d*36 + tx*2 + 1];
            float a[8] = {a0.x,a0.y,a0.z,a0.w,a1.x,a1.y,a1.z,a1.w};
            #pragma unroll
            for (int rr = 0; rr < 8; rr++) { s[rr][0] += a[rr]*b0; s[rr][1] += a[rr]*b1; }
        }
        #pragma unroll
        for (int rr = 0; rr < 8; rr++) {
            int mg = m0 + ty*8 + rr;
            #pragma unroll
            for (int j = 0; j < 2; j++) {
                int ng = n0 + tx*2 + j;
                float v = (mg >= ng) ? s[rr][j]*__expf(-sl*(float)(mg-ng)) : 0.f;
                ScT[(tx*2 + j)*132 + ty*8 + rr] = v;
            }
        }
        __syncthreads();
        #pragma unroll
        for (int n = 0; n < 32; n++) {
            float4 a0 = *(const float4*)&ScT[n*132 + ty*8];
            float4 a1 = *(const float4*)&ScT[n*132 + ty*8 + 4];
            float4 b0 = *(const float4*)&Vs[n*132 + tx*8];
            float4 b1 = *(const float4*)&Vs[n*132 + tx*8 + 4];
            float a[8] = {a0.x,a0.y,a0.z,a0.w,a1.x,a1.y,a1.z,a1.w};
            float b[8] = {b0.x,b0.y,b0.z,b0.w,b1.x,b1.y,b1.z,b1.w};
            #pragma unroll
            for (int rr = 0; rr < 8; rr++)
                #pragma unroll
                for (int cc = 0; cc < 8; cc++) acc[rr][cc] += a[rr]*b[cc];
        }
        __syncthreads();
    }

    #pragma unroll
    for (int rr = 0; rr < 8; rr++) {
        float* op = g_attn + (size_t)(blk*BLK + m0 + ty*8 + rr)*HID + h*HD + tx*8;
        #pragma unroll
        for (int cc = 0; cc < 8; cc++) op[cc] = acc[rr][cc];
    }
}

// ---------------- final combine ----------------
__global__ void combine_kernel(const float* __restrict__ hid2, const float* __restrict__ yslot,
                               const float* __restrict__ sw, float* __restrict__ out)
{
    int idx = blockIdx.x*256 + threadIdx.x;
    int n = idx / HID; int c = idx % HID;
    out[idx] = hid2[idx]
             + sw[n*2]   * yslot[(size_t)(n*2)  *HID + c]
             + sw[n*2+1] * yslot[(size_t)(n*2+1)*HID + c];
}

// ---------------- launch ----------------
extern "C" void kernel_launch(void* const* d_in, const int* in_sizes, int n_in,
                              void* d_out, int out_size)
{
    (void)in_sizes; (void)n_in; (void)out_size;
    const float* x     = (const float*)d_in[0];
    const float* slope = (const float*)d_in[1];
    const float* ln1   = (const float*)d_in[2];
    const float* ln2   = (const float*)d_in[3];
    const float* qkvw  = (const float*)d_in[4];
    const float* ogw   = (const float*)d_in[5];
    const float* anw   = (const float*)d_in[6];
    const float* aow   = (const float*)d_in[7];
    const float* rw    = (const float*)d_in[8];
    const float* w1    = (const float*)d_in[9];
    const float* w2    = (const float*)d_in[10];
    const float* w3    = (const float*)d_in[11];
    float* out = (float*)d_out;

    float *p_h, *p_qkv, *p_gate, *p_attn, *p_attnng, *p_hid2, *p_h2;
    float *p_act, *p_act2, *p_yslot, *p_slotw;
    int *p_btok, *p_bdst, *p_cnt;
    cudaGetSymbolAddress((void**)&p_h, g_h);
    cudaGetSymbolAddress((void**)&p_qkv, g_qkv);
    cudaGetSymbolAddress((void**)&p_gate, g_gate);
    cudaGetSymbolAddress((void**)&p_attn, g_attn);
    cudaGetSymbolAddress((void**)&p_attnng, g_attnng);
    cudaGetSymbolAddress((void**)&p_hid2, g_hid2);
    cudaGetSymbolAddress((void**)&p_h2, g_h2);
    cudaGetSymbolAddress((void**)&p_act, g_act);
    cudaGetSymbolAddress((void**)&p_act2, g_act2);
    cudaGetSymbolAddress((void**)&p_yslot, g_yslot);
    cudaGetSymbolAddress((void**)&p_slotw, g_slotw);
    cudaGetSymbolAddress((void**)&p_btok, g_btok);
    cudaGetSymbolAddress((void**)&p_bdst, g_bdst);
    cudaGetSymbolAddress((void**)&p_cnt, g_cnt);

    cudaFuncSetAttribute(attn_out_kernel, cudaFuncAttributeMaxDynamicSharedMemorySize, ATTN_SMEM);
    cudaFuncSetAttribute(bgemm_std_kernel, cudaFuncAttributeMaxDynamicSharedMemorySize, BG_SMEM);
    cudaFuncSetAttribute(bgemm_qkvgate_kernel, cudaFuncAttributeMaxDynamicSharedMemorySize, BG_SMEM);
    cudaFuncSetAttribute(moe_s12_kernel, cudaFuncAttributeMaxDynamicSharedMemorySize, BG_SMEM);
    cudaFuncSetAttribute(moe_s3_kernel, cudaFuncAttributeMaxDynamicSharedMemorySize, BG_SMEM);

    // 1. rmsnorm1
    rmsnorm_kernel<<<NTOK, 256>>>(x, ln1, p_h, 1e-5f);
    // 2. fused qkv (silu) + gate (sigmoid)
    bgemm_qkvgate_kernel<<<dim3(QKVD/128 + HID/128, NTOK/128), 256, BG_SMEM>>>(
        p_h, qkvw, ogw, p_qkv, p_gate);
    // 3-5. lightning attention
    kv_contrib_kernel<<<dim3(NBLK, NH, 2), 256>>>(slope);
    kv_prefix_kernel<<<dim3(NBLK, NH), 256>>>(slope);
    attn_out_kernel<<<dim3(2, NBLK, NH), 256, ATTN_SMEM>>>(slope);
    // 6. rmsnorm(attn)*gate
    rmsnorm_gate_kernel<<<NTOK, 256>>>(p_attn, anw, p_gate, p_attnng);
    // 7. hid2 = x + attnng @ aout_w^T
    bgemm_std_kernel<<<dim3(HID/128, NTOK/128), 256, BG_SMEM>>>(
        p_attnng, aow, x, p_hid2, NTOK, HID, HID, 3);
    // 8. rmsnorm2
    rmsnorm_kernel<<<NTOK, 256>>>(p_hid2, ln2, p_h2, 1e-5f);
    // 9-10. routing
    zero_cnt_kernel<<<1, 32>>>(p_cnt);
    router_kernel<<<NTOK, 256>>>(p_h2, rw, p_slotw, p_btok, p_bdst, p_cnt);
    // 11. fused MoE stage1+stage2 (w1->act silu, w3->act2)
    moe_s12_kernel<<<dim3(FFN/128, NTOK/128, 2*NEXP), 256, BG_SMEM>>>(
        p_h2, w1, w3, p_act, p_act2, p_btok, p_bdst, p_cnt);
    // 12. MoE stage3: yslot = (act*act2) @ w2^T
    moe_s3_kernel<<<dim3(HID/128, NTOK/128, NEXP), 256, BG_SMEM>>>(
        p_act, p_act2, w2, p_yslot, p_bdst, p_cnt);
    // 13. out = hid2 + sum_k w_k * y_k
    combine_kernel<<<NTOK*HID/256, 256>>>(p_hid2, p_yslot, p_slotw, out);
}

// round 14
// speedup vs baseline: 1.0305x; 1.0305x over previous
#include <cuda_runtime.h>
#include <cuda_bf16.h>
#include <math.h>
#include <stdint.h>

#define NTOK 1024
#define HID  2048
#define NH   16
#define HD   128
#define QKVD 6144
#define FFN  2048
#define NEXP 8
#define TK   2
#define BLK  256
#define NBLK 4

// ---------------- scratch (static device globals; no allocs) ----------------
__device__ float g_h[NTOK*HID];
__device__ float g_qkv[NTOK*QKVD];
__device__ float g_gate[NTOK*HID];
__device__ float g_attn[NTOK*HID];
__device__ float g_attnng[NTOK*HID];
__device__ float g_hid2[NTOK*HID];
__device__ float g_h2[NTOK*HID];
__device__ float g_kvC[2*NH*NBLK*HD*HD];   // two row-half partials
__device__ float g_kvin[NH*NBLK*HD*HD];
__device__ float g_act[NTOK*TK*FFN];       // silu(h2@w1) per slot
__device__ float g_act2[NTOK*TK*FFN];      // h2@w3 per slot
__device__ float g_yslot[NTOK*TK*HID];
__device__ float g_slotw[NTOK*TK];
__device__ int   g_btok[NEXP*NTOK];
__device__ int   g_bdst[NEXP*NTOK];
__device__ int   g_cnt[NEXP];

// ---------------- mma.sync bf16 + ldmatrix ----------------
__device__ __forceinline__ void mma_bf16(float* c,
    uint32_t a0, uint32_t a1, uint32_t a2, uint32_t a3, uint32_t b0, uint32_t b1)
{
    asm volatile(
        "mma.sync.aligned.m16n8k16.row.col.f32.bf16.bf16.f32 "
        "{%0,%1,%2,%3}, {%4,%5,%6,%7}, {%8,%9}, {%0,%1,%2,%3};"
        : "+f"(c[0]), "+f"(c[1]), "+f"(c[2]), "+f"(c[3])
        : "r"(a0), "r"(a1), "r"(a2), "r"(a3), "r"(b0), "r"(b1));
}

__device__ __forceinline__ void ldsm4(uint32_t* r, uint32_t addr)
{
    asm volatile("ldmatrix.sync.aligned.m8n8.x4.shared.b16 {%0,%1,%2,%3}, [%4];"
        : "=r"(r[0]), "=r"(r[1]), "=r"(r[2]), "=r"(r[3]) : "r"(addr));
}

__device__ __forceinline__ uint32_t smem_u32(const void* p) {
    uint32_t a;
    asm("{ .reg .u64 t; cvta.to.shared.u64 t, %1; cvt.u32.u64 %0, t; }" : "=r"(a) : "l"(p));
    return a;
}

// fp32 pair -> bf16x2 hi + bf16x2 lo (residual); x in low half, y in high half
__device__ __forceinline__ void cvt_split(float x, float y, uint32_t& hi, uint32_t& lo)
{
    asm("cvt.rn.satfinite.bf16x2.f32 %0, %1, %2;" : "=r"(hi) : "f"(y), "f"(x));
    float hx = __uint_as_float(hi << 16);
    float hy = __uint_as_float(hi & 0xFFFF0000u);
    float lx = x - hx, ly = y - hy;
    asm("cvt.rn.satfinite.bf16x2.f32 %0, %1, %2;" : "=r"(lo) : "f"(ly), "f"(lx));
}

// ---------------- split-bf16 tensor GEMM: C[M,N] = epi(A[M,K] @ B[N,K]^T) ------
// CTA tile 128x128, 8 warps (4 along M x 2 along N), warp tile 32x64.
// K chunked by 32; smem tiles: Ahi/Alo/Bhi/Blo, 128 rows x 32 bf16, pitch 40
// bf16 (20 words); ldmatrix fragment loads are bank-conflict-free. Double buffer.
#define KC      32
#define PITCHW  20                    // 32-bit words per row (40 bf16)
#define TILEW   (128*PITCHW)          // words per tile
#define BUFW    (4*TILEW)             // words per buffer (Ahi,Alo,Bhi,Blo)
#define BG_SMEM (2*BUFW*4)            // bytes total (two buffers)

// EPI: 0 none, 1 silu, 2 sigmoid, 3 +Res ; HASMUL: A-elements multiplied by A2
template<int EPI, bool HASMUL>
__device__ __forceinline__ void gemm_body(
    const float* __restrict__ A, const float* __restrict__ A2,
    const float* __restrict__ B,
    const float* __restrict__ Res, float* __restrict__ C,
    int N, int K, int bm, int bn, int mrows,
    const int* __restrict__ gat, const int* __restrict__ sca)
{
    extern __shared__ uint32_t smw[];   // word-addressed smem
    uint32_t sbase = smem_u32(smw);

    int tid = threadIdx.x, wid = tid >> 5, lane = tid & 31;
    int wm = wid & 3, wn = wid >> 2;            // warp tile: rows wm*32, cols wn*64
    int mrow = lane & 7, mat = lane >> 3;
    uint32_t aoff[2], boff[4];
    #pragma unroll
    for (int i = 0; i < 2; i++)
        aoff[i] = (uint32_t)(((wm*32 + i*16 + ((mat & 1) << 3) + mrow)*PITCHW
                              + ((mat >> 1) << 2)) * 4);
    #pragma unroll
    for (int g = 0; g < 4; g++)
        boff[g] = (uint32_t)(((wn*64 + (2*g + (mat >> 1))*8 + mrow)*PITCHW
                              + ((mat & 1) << 2)) * 4);

    // loader mapping: row = tid>>1 (0..127), half selects 16 k-values
    int lrow = tid >> 1, half = tid & 1;
    int ar = bm + lrow; if (ar >= mrows) ar = mrows - 1;
    int arix = gat ? gat[ar] : ar;
    const float* Arow  = A + (size_t)arix*K + half*16;
    const float* A2row = HASMUL ? A2 + (size_t)arix*K + half*16 : nullptr;
    const float* Brow  = B + (size_t)(bn + lrow)*K + half*16;

    float acc[2][8][4];
    #pragma unroll
    for (int i = 0; i < 2; i++)
        #pragma unroll
        for (int j = 0; j < 8; j++)
            #pragma unroll
            for (int q = 0; q < 4; q++) acc[i][j][q] = 0.f;

    float4 pa[4], pb[4];
    auto prefetch = [&](int t) {
        const float* Ap = Arow + t*KC;
        const float* Bp = Brow + t*KC;
        #pragma unroll
        for (int j = 0; j < 4; j++) {
            pa[j] = *(const float4*)(Ap + j*4);
            pb[j] = *(const float4*)(Bp + j*4);
        }
        if (HASMUL) {
            const float* Mp = A2row + t*KC;
            #pragma unroll
            for (int j = 0; j < 4; j++) {
                float4 m = *(const float4*)(Mp + j*4);
                pa[j].x *= m.x; pa[j].y *= m.y; pa[j].z *= m.z; pa[j].w *= m.w;
            }
        }
    };

    int ntiles = K / KC;
    int swbase = lrow*PITCHW + half*8;          // word offset of this thread's stores

    // store prefetched regs into buffer `buf` (uint2 = STS.64)
    auto store_tiles = [&](int buf) {
        uint32_t* Ah = smw + buf*BUFW;
        uint32_t* Al = Ah + TILEW;
        uint32_t* Bh = Al + TILEW;
        uint32_t* Bl = Bh + TILEW;
        #pragma unroll
        for (int j = 0; j < 4; j++) {
            uint32_t h0, l0, h1, l1;
            int o = swbase + j*2;
            cvt_split(pa[j].x, pa[j].y, h0, l0);
            cvt_split(pa[j].z, pa[j].w, h1, l1);
            *(uint2*)(Ah + o) = make_uint2(h0, h1);
            *(uint2*)(Al + o) = make_uint2(l0, l1);
            cvt_split(pb[j].x, pb[j].y, h0, l0);
            cvt_split(pb[j].z, pb[j].w, h1, l1);
            *(uint2*)(Bh + o) = make_uint2(h0, h1);
            *(uint2*)(Bl + o) = make_uint2(l0, l1);
        }
    };

    prefetch(0);
    store_tiles(0);
    __syncthreads();

    for (int t = 0; t < ntiles; t++) {
        int buf = t & 1;
        if (t + 1 < ntiles) prefetch(t + 1);

        uint32_t bAh = sbase + (uint32_t)(buf*BUFW*4);
        uint32_t bAl = bAh + TILEW*4;
        uint32_t bBh = bAl + TILEW*4;
        uint32_t bBl = bBh + TILEW*4;

        #pragma unroll
        for (int ks = 0; ks < 2; ks++) {        // two k16 steps per chunk
            uint32_t ks32 = (uint32_t)(ks*32);
            uint32_t ah[2][4], al[2][4], bh[4][4], bl[4][4];
            #pragma unroll
            for (int i = 0; i < 2; i++) {
                ldsm4(ah[i], bAh + aoff[i] + ks32);
                ldsm4(al[i], bAl + aoff[i] + ks32);
            }
            #pragma unroll
            for (int g = 0; g < 4; g++) {
                ldsm4(bh[g], bBh + boff[g] + ks32);
                ldsm4(bl[g], bBl + boff[g] + ks32);
            }
            #pragma unroll
            for (int i = 0; i < 2; i++)
                #pragma unroll
                for (int j = 0; j < 8; j++) {
                    int g = j >> 1, o = (j & 1)*2;
                    mma_bf16(acc[i][j], ah[i][0], ah[i][1], ah[i][2], ah[i][3], bh[g][o], bh[g][o+1]);
                    mma_bf16(acc[i][j], ah[i][0], ah[i][1], ah[i][2], ah[i][3], bl[g][o], bl[g][o+1]);
                    mma_bf16(acc[i][j], al[i][0], al[i][1], al[i][2], al[i][3], bh[g][o], bh[g][o+1]);
                }
        }
        if (t + 1 < ntiles) store_tiles(buf ^ 1);
        __syncthreads();
    }

    // epilogue: c fragment (etq row group, etr k-pair -> cols etr*2, etr*2+1)
    int etq = lane >> 2, etr = lane & 3;
    #pragma unroll
    for (int i = 0; i < 2; i++) {
        #pragma unroll
        for (int half8 = 0; half8 < 2; half8++) {   // c0,c1 (row tq) / c2,c3 (row tq+8)
            int gm = bm + wm*32 + i*16 + half8*8 + etq;
            if (gm < mrows) {
                int orow = sca ? sca[gm] : gm;
                #pragma unroll
                for (int j = 0; j < 8; j++) {
                    int col = bn + wn*64 + j*8 + etr*2;
                    float vx = acc[i][j][half8*2 + 0];
                    float vy = acc[i][j][half8*2 + 1];
                    float* cp = C + (size_t)orow*N + col;
                    if (EPI == 1) {
                        vx = vx/(1.f + __expf(-vx)); vy = vy/(1.f + __expf(-vy));
                    } else if (EPI == 2) {
                        vx = 1.f/(1.f + __expf(-vx)); vy = 1.f/(1.f + __expf(-vy));
                    } else if (EPI == 3) {
                        const float* rp = Res + (size_t)gm*N + col;
                        vx += rp[0]; vy += rp[1];
                    }
                    cp[0] = vx; cp[1] = vy;
                }
            }
        }
    }
}

// dense GEMM (templated epilogue)
template<int EPI>
__global__ void __launch_bounds__(256) bgemm_kernel(
    const float* __restrict__ A, const float* __restrict__ B,
    const float* __restrict__ Res, float* __restrict__ C,
    int M, int N, int K)
{
    gemm_body<EPI, false>(A, nullptr, B, Res, C, N, K,
                          blockIdx.y*128, blockIdx.x*128, M, nullptr, nullptr);
}

// fused MoE stage1+stage2: z<8 -> w1/silu->act ; z>=8 -> w3/none->act2
__global__ void __launch_bounds__(256) moe_s12_kernel(
    const float* __restrict__ A, const float* __restrict__ w1,
    const float* __restrict__ w3, float* __restrict__ act, float* __restrict__ act2,
    const int* __restrict__ btok, const int* __restrict__ bdst,
    const int* __restrict__ cnt)
{
    int z = blockIdx.z, e = z & 7;
    int mrows = cnt[e];
    int bm = blockIdx.y*128;
    if (bm >= mrows) return;
    if (z < 8)
        gemm_body<1, false>(A, nullptr, w1 + (size_t)e*FFN*HID, nullptr, act,
                            FFN, HID, bm, blockIdx.x*128, mrows,
                            btok + e*NTOK, bdst + e*NTOK);
    else
        gemm_body<0, false>(A, nullptr, w3 + (size_t)e*FFN*HID, nullptr, act2,
                            FFN, HID, bm, blockIdx.x*128, mrows,
                            btok + e*NTOK, bdst + e*NTOK);
}

// MoE stage3: A = act (*) act2 (elementwise in loader), B = w2
__global__ void __launch_bounds__(256) moe_s3_kernel(
    const float* __restrict__ act, const float* __restrict__ act2,
    const float* __restrict__ w2, float* __restrict__ yslot,
    const int* __restrict__ bdst, const int* __restrict__ cnt)
{
    int e = blockIdx.z;
    int mrows = cnt[e];
    int bm = blockIdx.y*128;
    if (bm >= mrows) return;
    gemm_body<0, true>(act, act2, w2 + (size_t)e*HID*FFN, nullptr, yslot,
                       HID, FFN, bm, blockIdx.x*128, mrows,
                       bdst + e*NTOK, bdst + e*NTOK);
}

// ---------------- rmsnorm ----------------
__global__ void rmsnorm_kernel(const float* __restrict__ in, const float* __restrict__ w,
                               float* __restrict__ out, float eps)
{
    int n = blockIdx.x; int tid = threadIdx.x;
    const float* row = in + (size_t)n*HID;
    float s = 0.f;
    for (int c = tid; c < HID; c += 256) { float v = row[c]; s += v*v; }
    __shared__ float red[256];
    red[tid] = s; __syncthreads();
    for (int o = 128; o > 0; o >>= 1) { if (tid < o) red[tid] += red[tid+o]; __syncthreads(); }
    float inv = rsqrtf(red[0]/(float)HID + eps);
    float* orow = out + (size_t)n*HID;
    for (int c = tid; c < HID; c += 256) orow[c] = row[c]*inv*w[c];
}

__global__ void rmsnorm_gate_kernel(const float* __restrict__ in, const float* __restrict__ w,
                                    const float* __restrict__ gate, float* __restrict__ out)
{
    int n = blockIdx.x; int tid = threadIdx.x;
    const float* row = in + (size_t)n*HID;
    float s = 0.f;
    for (int c = tid; c < HID; c += 256) { float v = row[c]; s += v*v; }
    __shared__ float red[256];
    red[tid] = s; __syncthreads();
    for (int o = 128; o > 0; o >>= 1) { if (tid < o) red[tid] += red[tid+o]; __syncthreads(); }
    float inv = rsqrtf(red[0]/(float)HID + 1.1920929e-07f);
    const float* grow = gate + (size_t)n*HID;
    float* orow = out + (size_t)n*HID;
    for (int c = tid; c < HID; c += 256) orow[c] = row[c]*inv*w[c]*grow[c];
}

// ---------------- router + routing ----------------
__global__ void zero_cnt_kernel(int* cnt) { if (threadIdx.x < NEXP) cnt[threadIdx.x] = 0; }

__global__ void router_kernel(const float* __restrict__ h2, const float* __restrict__ rw,
                              float* __restrict__ slotw, int* __restrict__ btok,
                              int* __restrict__ bdst, int* __restrict__ cnt)
{
    int n = blockIdx.x; int tid = threadIdx.x;
    int e = tid >> 5, lane = tid & 31;
    const float* xr = h2 + (size_t)n*HID;
    const float* wr = rw + (size_t)e*HID;
    float s = 0.f;
    for (int k = lane; k < HID; k += 32) s += xr[k]*wr[k];
    for (int o = 16; o > 0; o >>= 1) s += __shfl_down_sync(0xffffffffu, s, o);
    __shared__ float lg[NEXP];
    if (lane == 0) lg[e] = s;
    __syncthreads();
    if (tid == 0) {
        float m = lg[0];
        for (int i = 1; i < NEXP; i++) m = fmaxf(m, lg[i]);
        float p[NEXP];
        for (int i = 0; i < NEXP; i++) p[i] = expf(lg[i]-m);
        int i0 = 0;
        for (int i = 1; i < NEXP; i++) if (p[i] > p[i0]) i0 = i;
        int i1 = (i0 == 0) ? 1 : 0;
        for (int i = 0; i < NEXP; i++) if (i != i0 && p[i] > p[i1]) i1 = i;
        float inv = 1.f/(p[i0]+p[i1]);
        slotw[n*2]   = p[i0]*inv;
        slotw[n*2+1] = p[i1]*inv;
        int pos0 = atomicAdd(&cnt[i0], 1); btok[i0*NTOK+pos0] = n; bdst[i0*NTOK+pos0] = n*2;
        int pos1 = atomicAdd(&cnt[i1], 1); btok[i1*NTOK+pos1] = n; bdst[i1*NTOK+pos1] = n*2+1;
    }
}

// ---------------- attention: per-block KV contribution (2 row-half partials) --
__global__ void __launch_bounds__(256) kv_contrib_kernel(const float* __restrict__ slope)
{
    int blk = blockIdx.x, h = blockIdx.y, part = blockIdx.z;
    float sl = slope[h];
    __shared__ float Ks[32][132];
    __shared__ float Vs[32][132];
    int tid = threadIdx.x, ty = tid >> 4, tx = tid & 15;
    int lrow = tid >> 3, cb = tid & 7;

    float acc[8][8];
    #pragma unroll
    for (int i = 0; i < 8; i++)
        #pragma unroll
        for (int j = 0; j < 8; j++) acc[i][j] = 0.f;

    for (int i0 = 0; i0 < 128; i0 += 32) {
        int rowin = part*128 + i0 + lrow;
        int gi = blk*BLK + rowin;
        float kd = __expf(-sl*(float)(BLK - (rowin + 1)));
        const float* kp = g_qkv + (size_t)gi*QKVD + h*384 + 128;
        #pragma unroll
        for (int j = 0; j < 4; j++) {
            int c = (cb + j*8)*4;
            float4 kv = *(const float4*)(kp + c);
            Ks[lrow][c+0] = kv.x*kd; Ks[lrow][c+1] = kv.y*kd;
            Ks[lrow][c+2] = kv.z*kd; Ks[lrow][c+3] = kv.w*kd;
            float4 vv = *(const float4*)(kp + 128 + c);
            *(float4*)&Vs[lrow][c] = vv;
        }
        __syncthreads();
        #pragma unroll
        for (int i = 0; i < 32; i++) {
            float4 a0 = *(const float4*)&Ks[i][ty*8];
            float4 a1 = *(const float4*)&Ks[i][ty*8+4];
            float4 b0 = *(const float4*)&Vs[i][tx*8];
            float4 b1 = *(const float4*)&Vs[i][tx*8+4];
            float a[8] = {a0.x,a0.y,a0.z,a0.w,a1.x,a1.y,a1.z,a1.w};
            float b[8] = {b0.x,b0.y,b0.z,b0.w,b1.x,b1.y,b1.z,b1.w};
            #pragma unroll
            for (int rr = 0; rr < 8; rr++)
                #pragma unroll
                for (int cc = 0; cc < 8; cc++) acc[rr][cc] += a[rr]*b[cc];
        }
        __syncthreads();
    }
    float* cp = g_kvC + (size_t)((part*NH + h)*NBLK + blk)*HD*HD;
    #pragma unroll
    for (int rr = 0; rr < 8; rr++)
        #pragma unroll
        for (int cc = 0; cc < 8; cc++)
            cp[(size_t)(ty*8+rr)*HD + tx*8 + cc] = acc[rr][cc];
}

// kv_in(i) = sum_{j<i} bdecay^{i-1-j} (C0_j + C1_j)  -- x-plane split 4 ways
__global__ void kv_prefix_kernel(const float* __restrict__ slope)
{
    int i = blockIdx.x, h = blockIdx.y, zs = blockIdx.z, tid = threadIdx.x;
    float bd = __expf(-slope[h]*(float)BLK);
    const float* b0 = g_kvC + (size_t)(h*NBLK)*HD*HD;
    const float* b1 = g_kvC + (size_t)((NH + h)*NBLK)*HD*HD;
    float* outp = g_kvin + (size_t)(h*NBLK + i)*HD*HD;
    int x0 = zs*(HD*HD/4);
    for (int x = x0 + tid; x < x0 + HD*HD/4; x += 256) {
        float s = 0.f, w = 1.f;
        for (int j = i-1; j >= 0; j--) {
            float cj = b0[(size_t)j*HD*HD + x] + b1[(size_t)j*HD*HD + x];
            s += w*cj; w *= bd;
        }
        outp[x] = s;
    }
}

#define ATTN_SMEM ((128*132 + 128*36 + 32*132 + 32*132)*4)
__global__ void __launch_bounds__(256) attn_out_kernel(const float* __restrict__ slope)
{
    int m0 = blockIdx.x*128;
    int blk = blockIdx.y;
    int h = blockIdx.z;
    float sl = slope[h];

    extern __shared__ float sm[];
    float* QsT = sm;
    float* KsT = QsT + 128*132;
    float* Vs  = KsT + 128*36;
    float* ScT = Vs  + 32*132;

    int tid = threadIdx.x, ty = tid >> 4, tx = tid & 15;

    {
        int m = tid >> 1, half = tid & 1;
        const float* qp = g_qkv + (size_t)(blk*BLK + m0 + m)*QKVD + h*384;
        #pragma unroll
        for (int j = 0; j < 16; j++) {
            int d = (half*16 + j)*4;
            float4 q = *(const float4*)(qp + d);
            QsT[(d+0)*132 + m] = q.x; QsT[(d+1)*132 + m] = q.y;
            QsT[(d+2)*132 + m] = q.z; QsT[(d+3)*132 + m] = q.w;
        }
    }
    float qd[8];
    #pragma unroll
    for (int i = 0; i < 8; i++) qd[i] = __expf(-sl*(float)(m0 + ty*8 + i + 1));

    float acc[8][8];
    #pragma unroll
    for (int i = 0; i < 8; i++)
        #pragma unroll
        for (int j = 0; j < 8; j++) acc[i][j] = 0.f;
    __syncthreads();

    int lrow = tid >> 3, cb = tid & 7;

    const float* kvp = g_kvin + (size_t)(h*NBLK + blk)*HD*HD;
    for (int dc = 0; dc < 4; dc++) {
        #pragma unroll
        for (int j = 0; j < 4; j++) {
            int c = (cb + j*8)*4;
            float4 v = *(const float4*)(kvp + (size_t)(dc*32 + lrow)*HD + c);
            *(float4*)&Vs[lrow*132 + c] = v;
        }
        __syncthreads();
        #pragma unroll
        for (int i = 0; i < 32; i++) {
            int d = dc*32 + i;
            float4 a0 = *(const float4*)&QsT[d*132 + ty*8];
            float4 a1 = *(const float4*)&QsT[d*132 + ty*8 + 4];
            float4 b0 = *(const float4*)&Vs[i*132 + tx*8];
            float4 b1 = *(const float4*)&Vs[i*132 + tx*8 + 4];
            float a[8] = {a0.x,a0.y,a0.z,a0.w,a1.x,a1.y,a1.z,a1.w};
            float b[8] = {b0.x,b0.y,b0.z,b0.w,b1.x,b1.y,b1.z,b1.w};
            #pragma unroll
            for (int rr = 0; rr < 8; rr++) {
                float av = a[rr]*qd[rr];
                #pragma unroll
                for (int cc = 0; cc < 8; cc++) acc[rr][cc] += av*b[cc];
            }
        }
        __syncthreads();
    }

    int ncmax = (m0 + 128)/32;
    for (int nc = 0; nc < ncmax; nc++) {
        int n0 = nc*32;
        const float* kp = g_qkv + (size_t)(blk*BLK + n0 + lrow)*QKVD + h*384 + 128;
        #pragma unroll
        for (int j = 0; j < 4; j++) {
            int d = (cb + j*8)*4;
            float4 kv = *(const float4*)(kp + d);
            KsT[(d+0)*36 + lrow] = kv.x; KsT[(d+1)*36 + lrow] = kv.y;
            KsT[(d+2)*36 + lrow] = kv.z; KsT[(d+3)*36 + lrow] = kv.w;
            float4 vv = *(const float4*)(kp + 128 + d);
            *(float4*)&Vs[lrow*132 + d] = vv;
        }
        __syncthreads();

        float s[8][2];
        #pragma unroll
        for (int rr = 0; rr < 8; rr++) { s[rr][0] = 0.f; s[rr][1] = 0.f; }
        for (int d = 0; d < 128; d++) {
            float4 a0 = *(const float4*)&QsT[d*132 + ty*8];
            float4 a1 = *(const float4*)&QsT[d*132 + ty*8 + 4];
            float b0 = KsT[d*36 + tx*2], b1 = KsT[d*36 + tx*2 + 1];
            float a[8] = {a0.x,a0.y,a0.z,a0.w,a1.x,a1.y,a1.z,a1.w};
            #pragma unroll
            for (int rr = 0; rr < 8; rr++) { s[rr][0] += a[rr]*b0; s[rr][1] += a[rr]*b1; }
        }
        #pragma unroll
        for (int rr = 0; rr < 8; rr++) {
            int mg = m0 + ty*8 + rr;
            #pragma unroll
            for (int j = 0; j < 2; j++) {
                int ng = n0 + tx*2 + j;
                float v = (mg >= ng) ? s[rr][j]*__expf(-sl*(float)(mg-ng)) : 0.f;
                ScT[(tx*2 + j)*132 + ty*8 + rr] = v;
            }
        }
        __syncthreads();
        #pragma unroll
        for (int n = 0; n < 32; n++) {
            float4 a0 = *(const float4*)&ScT[n*132 + ty*8];
            float4 a1 = *(const float4*)&ScT[n*132 + ty*8 + 4];
            float4 b0 = *(const float4*)&Vs[n*132 + tx*8];
            float4 b1 = *(const float4*)&Vs[n*132 + tx*8 + 4];
            float a[8] = {a0.x,a0.y,a0.z,a0.w,a1.x,a1.y,a1.z,a1.w};
            float b[8] = {b0.x,b0.y,b0.z,b0.w,b1.x,b1.y,b1.z,b1.w};
            #pragma unroll
            for (int rr = 0; rr < 8; rr++)
                #pragma unroll
                for (int cc = 0; cc < 8; cc++) acc[rr][cc] += a[rr]*b[cc];
        }
        __syncthreads();
    }

    #pragma unroll
    for (int rr = 0; rr < 8; rr++) {
        float* op = g_attn + (size_t)(blk*BLK + m0 + ty*8 + rr)*HID + h*HD + tx*8;
        #pragma unroll
        for (int cc = 0; cc < 8; cc++) op[cc] = acc[rr][cc];
    }
}

// ---------------- final combine ----------------
__global__ void combine_kernel(const float* __restrict__ hid2, const float* __restrict__ yslot,
                               const float* __restrict__ sw, float* __restrict__ out)
{
    int idx = blockIdx.x*256 + threadIdx.x;
    int n = idx / HID; int c = idx % HID;
    out[idx] = hid2[idx]
             + sw[n*2]   * yslot[(size_t)(n*2)  *HID + c]
             + sw[n*2+1] * yslot[(size_t)(n*2+1)*HID + c];
}

// ---------------- launch ----------------
extern "C" void kernel_launch(void* const* d_in, const int* in_sizes, int n_in,
                              void* d_out, int out_size)
{
    (void)in_sizes; (void)n_in; (void)out_size;
    const float* x     = (const float*)d_in[0];
    const float* slope = (const float*)d_in[1];
    const float* ln1   = (const float*)d_in[2];
    const float* ln2   = (const float*)d_in[3];
    const float* qkvw  = (const float*)d_in[4];
    const float* ogw   = (const float*)d_in[5];
    const float* anw   = (const float*)d_in[6];
    const float* aow   = (const float*)d_in[7];
    const float* rw    = (const float*)d_in[8];
    const float* w1    = (const float*)d_in[9];
    const float* w2    = (const float*)d_in[10];
    const float* w3    = (const float*)d_in[11];
    float* out = (float*)d_out;

    float *p_h, *p_qkv, *p_gate, *p_attn, *p_attnng, *p_hid2, *p_h2;
    float *p_act, *p_act2, *p_yslot, *p_slotw;
    int *p_btok, *p_bdst, *p_cnt;
    cudaGetSymbolAddress((void**)&p_h, g_h);
    cudaGetSymbolAddress((void**)&p_qkv, g_qkv);
    cudaGetSymbolAddress((void**)&p_gate, g_gate);
    cudaGetSymbolAddress((void**)&p_attn, g_attn);
    cudaGetSymbolAddress((void**)&p_attnng, g_attnng);
    cudaGetSymbolAddress((void**)&p_hid2, g_hid2);
    cudaGetSymbolAddress((void**)&p_h2, g_h2);
    cudaGetSymbolAddress((void**)&p_act, g_act);
    cudaGetSymbolAddress((void**)&p_act2, g_act2);
    cudaGetSymbolAddress((void**)&p_yslot, g_yslot);
    cudaGetSymbolAddress((void**)&p_slotw, g_slotw);
    cudaGetSymbolAddress((void**)&p_btok, g_btok);
    cudaGetSymbolAddress((void**)&p_bdst, g_bdst);
    cudaGetSymbolAddress((void**)&p_cnt, g_cnt);

    cudaFuncSetAttribute(attn_out_kernel, cudaFuncAttributeMaxDynamicSharedMemorySize, ATTN_SMEM);
    cudaFuncSetAttribute(bgemm_kernel<1>, cudaFuncAttributeMaxDynamicSharedMemorySize, BG_SMEM);
    cudaFuncSetAttribute(bgemm_kernel<2>, cudaFuncAttributeMaxDynamicSharedMemorySize, BG_SMEM);
    cudaFuncSetAttribute(bgemm_kernel<3>, cudaFuncAttributeMaxDynamicSharedMemorySize, BG_SMEM);
    cudaFuncSetAttribute(moe_s12_kernel, cudaFuncAttributeMaxDynamicSharedMemorySize, BG_SMEM);
    cudaFuncSetAttribute(moe_s3_kernel, cudaFuncAttributeMaxDynamicSharedMemorySize, BG_SMEM);

    // 1. rmsnorm1
    rmsnorm_kernel<<<NTOK, 256>>>(x, ln1, p_h, 1e-5f);
    // 2. qkv = silu(h @ qkv_w^T)
    bgemm_kernel<1><<<dim3(QKVD/128, NTOK/128), 256, BG_SMEM>>>(
        p_h, qkvw, nullptr, p_qkv, NTOK, QKVD, HID);
    // 3. gate = sigmoid(h @ ogate_w^T)
    bgemm_kernel<2><<<dim3(HID/128, NTOK/128), 256, BG_SMEM>>>(
        p_h, ogw, nullptr, p_gate, NTOK, HID, HID);
    // 4-6. lightning attention
    kv_contrib_kernel<<<dim3(NBLK, NH, 2), 256>>>(slope);
    kv_prefix_kernel<<<dim3(NBLK, NH, 4), 256>>>(slope);
    attn_out_kernel<<<dim3(2, NBLK, NH), 256, ATTN_SMEM>>>(slope);
    // 7. rmsnorm(attn)*gate
    rmsnorm_gate_kernel<<<NTOK, 256>>>(p_attn, anw, p_gate, p_attnng);
    // 8. hid2 = x + attnng @ aout_w^T
    bgemm_kernel<3><<<dim3(HID/128, NTOK/128), 256, BG_SMEM>>>(
        p_attnng, aow, x, p_hid2, NTOK, HID, HID);
    // 9. rmsnorm2
    rmsnorm_kernel<<<NTOK, 256>>>(p_hid2, ln2, p_h2, 1e-5f);
    // 10-11. routing
    zero_cnt_kernel<<<1, 32>>>(p_cnt);
    router_kernel<<<NTOK, 256>>>(p_h2, rw, p_slotw, p_btok, p_bdst, p_cnt);
    // 12. fused MoE stage1+stage2 (w1->act silu, w3->act2), templated dispatch
    moe_s12_kernel<<<dim3(FFN/128, NTOK/128, 2*NEXP), 256, BG_SMEM>>>(
        p_h2, w1, w3, p_act, p_act2, p_btok, p_bdst, p_cnt);
    // 13. MoE stage3: yslot = (act*act2) @ w2^T
    moe_s3_kernel<<<dim3(HID/128, NTOK/128, NEXP), 256, BG_SMEM>>>(
        p_act, p_act2, w2, p_yslot, p_bdst, p_cnt);
    // 14. out = hid2 + sum_k w_k * y_k
    combine_kernel<<<NTOK*HID/256, 256>>>(p_hid2, p_yslot, p_slotw, out);
}

// round 17
// speedup vs baseline: 1.1000x; 1.0674x over previous
#include <cuda_runtime.h>
#include <cuda_bf16.h>
#include <math.h>
#include <stdint.h>

#define NTOK 1024
#define HID  2048
#define NH   16
#define HD   128
#define QKVD 6144
#define FFN  2048
#define NEXP 8
#define TK   2
#define BLK  256
#define NBLK 4

// ---------------- scratch (static device globals; no allocs) ----------------
__device__ float g_h[NTOK*HID];
__device__ float g_qkv[NTOK*QKVD];
__device__ float g_gate[NTOK*HID];
__device__ float g_attn[NTOK*HID];
__device__ float g_attnng[NTOK*HID];
__device__ float g_hid2[NTOK*HID];
__device__ float g_h2[NTOK*HID];
__device__ float g_kvC[2*NH*NBLK*HD*HD];   // two row-half partials
__device__ float g_kvin[NH*NBLK*HD*HD];
__device__ float g_act[NTOK*TK*FFN];
__device__ float g_yslot[NTOK*TK*HID];
__device__ float g_slotw[NTOK*TK];
__device__ int   g_btok[NEXP*NTOK];
__device__ int   g_bdst[NEXP*NTOK];
__device__ int   g_cnt[NEXP];

// ---------------- mma.sync bf16 + ldmatrix (baseline sm_80+/75+ features) ----
__device__ __forceinline__ void mma_bf16(float* c,
    uint32_t a0, uint32_t a1, uint32_t a2, uint32_t a3, uint32_t b0, uint32_t b1)
{
    asm volatile(
        "mma.sync.aligned.m16n8k16.row.col.f32.bf16.bf16.f32 "
        "{%0,%1,%2,%3}, {%4,%5,%6,%7}, {%8,%9}, {%0,%1,%2,%3};"
        : "+f"(c[0]), "+f"(c[1]), "+f"(c[2]), "+f"(c[3])
        : "r"(a0), "r"(a1), "r"(a2), "r"(a3), "r"(b0), "r"(b1));
}

__device__ __forceinline__ void ldsm4(uint32_t* r, uint32_t addr)
{
    asm volatile("ldmatrix.sync.aligned.m8n8.x4.shared.b16 {%0,%1,%2,%3}, [%4];"
        : "=r"(r[0]), "=r"(r[1]), "=r"(r[2]), "=r"(r[3]) : "r"(addr));
}

__device__ __forceinline__ uint32_t smem_u32(const void* p) {
    uint32_t a;
    asm("{ .reg .u64 t; cvta.to.shared.u64 t, %1; cvt.u32.u64 %0, t; }" : "=r"(a) : "l"(p));
    return a;
}

// fp32 pair -> bf16x2 hi + bf16x2 lo (residual); x in low half, y in high half
__device__ __forceinline__ void cvt_split(float x, float y, uint32_t& hi, uint32_t& lo)
{
    asm("cvt.rn.satfinite.bf16x2.f32 %0, %1, %2;" : "=r"(hi) : "f"(y), "f"(x));
    float hx = __uint_as_float(hi << 16);
    float hy = __uint_as_float(hi & 0xFFFF0000u);
    float lx = x - hx, ly = y - hy;
    asm("cvt.rn.satfinite.bf16x2.f32 %0, %1, %2;" : "=r"(lo) : "f"(ly), "f"(lx));
}

// ---------------- split-bf16 tensor GEMM: C[M,N] = epi(A[M,K] @ B[N,K]^T) ------
// CTA tile 128x128, 8 warps (4 along M x 2 along N), warp tile 32x64.
// K chunked by 32; smem tiles: Ahi/Alo/Bhi/Blo, 128 rows x 32 bf16, pitch 40
// bf16 (20 words); ldmatrix fragment loads are bank-conflict-free. Double buffer.
#define KC      32
#define PITCHW  20                    // 32-bit words per row (40 bf16)
#define TILEW   (128*PITCHW)          // words per tile
#define BUFW    (4*TILEW)             // words per buffer (Ahi,Alo,Bhi,Blo)
#define BG_SMEM (2*BUFW*4)            // bytes total (two buffers)

// EPI: 0 none, 1 silu, 2 sigmoid, 3 +Res, 5 C *= val
template<int EPI>
__global__ void __launch_bounds__(256) bgemm_kernel(
    const float* __restrict__ A, const float* __restrict__ Bbase, size_t bstride,
    const float* __restrict__ Res, float* __restrict__ C,
    int M, int N, int K,
    const int* __restrict__ gather, const int* __restrict__ scatter,
    const int* __restrict__ cnt)
{
    int e = blockIdx.z;
    int mrows = cnt ? cnt[e] : M;
    int bm = blockIdx.y*128, bn = blockIdx.x*128;
    if (bm >= mrows) return;
    const float* B = Bbase + (size_t)e*bstride;
    const int* gat = gather ? gather + e*NTOK : nullptr;
    const int* sca = scatter ? scatter + e*NTOK : nullptr;

    extern __shared__ uint32_t smw[];   // word-addressed smem
    uint32_t sbase = smem_u32(smw);

    int tid = threadIdx.x, wid = tid >> 5, lane = tid & 31;
    int wm = wid & 3, wn = wid >> 2;            // warp tile: rows wm*32, cols wn*64
    int tq = lane >> 2, tr = lane & 3;          // fragment row group / k-pair
    (void)tq; (void)tr;

    // ldmatrix per-lane byte offsets (within a tile)
    int mrow = lane & 7, mat = lane >> 3;
    uint32_t aoff[2], boff[4];
    #pragma unroll
    for (int i = 0; i < 2; i++)
        aoff[i] = (uint32_t)(((wm*32 + i*16 + ((mat & 1) << 3) + mrow)*PITCHW
                              + ((mat >> 1) << 2)) * 4);
    #pragma unroll
    for (int g = 0; g < 4; g++)
        boff[g] = (uint32_t)(((wn*64 + (2*g + (mat >> 1))*8 + mrow)*PITCHW
                              + ((mat & 1) << 2)) * 4);

    // loader mapping: row = tid>>1 (0..127), half selects 16 k-values
    int lrow = tid >> 1, half = tid & 1;
    int ar = bm + lrow; if (ar >= mrows) ar = mrows - 1;
    const float* Arow = A + (size_t)(gat ? gat[ar] : ar)*K + half*16;
    const float* Brow = B + (size_t)(bn + lrow)*K + half*16;

    float acc[2][8][4];
    #pragma unroll
    for (int i = 0; i < 2; i++)
        #pragma unroll
        for (int j = 0; j < 8; j++)
            #pragma unroll
            for (int q = 0; q < 4; q++) acc[i][j][q] = 0.f;

    float4 pa[4], pb[4];
    #pragma unroll
    for (int j = 0; j < 4; j++) {
        pa[j] = *(const float4*)(Arow + j*4);
        pb[j] = *(const float4*)(Brow + j*4);
    }

    int ntiles = K / KC;
    int swbase = lrow*PITCHW + half*8;          // word offset of this thread's stores

    // store prefetched regs into buffer `buf` (uint2 = STS.64)
    auto store_tiles = [&](int buf) {
        uint32_t* Ah = smw + buf*BUFW;
        uint32_t* Al = Ah + TILEW;
        uint32_t* Bh = Al + TILEW;
        uint32_t* Bl = Bh + TILEW;
        #pragma unroll
        for (int j = 0; j < 4; j++) {
            uint32_t h0, l0, h1, l1;
            int o = swbase + j*2;
            cvt_split(pa[j].x, pa[j].y, h0, l0);
            cvt_split(pa[j].z, pa[j].w, h1, l1);
            *(uint2*)(Ah + o) = make_uint2(h0, h1);
            *(uint2*)(Al + o) = make_uint2(l0, l1);
            cvt_split(pb[j].x, pb[j].y, h0, l0);
            cvt_split(pb[j].z, pb[j].w, h1, l1);
            *(uint2*)(Bh + o) = make_uint2(h0, h1);
            *(uint2*)(Bl + o) = make_uint2(l0, l1);
        }
    };

    store_tiles(0);
    __syncthreads();

    for (int t = 0; t < ntiles; t++) {
        int buf = t & 1;
        if (t + 1 < ntiles) {
            const float* Ap = Arow + (t+1)*KC;
            const float* Bp = Brow + (t+1)*KC;
            #pragma unroll
            for (int j = 0; j < 4; j++) {
                pa[j] = *(const float4*)(Ap + j*4);
                pb[j] = *(const float4*)(Bp + j*4);
            }
        }
        uint32_t bAh = sbase + (uint32_t)(buf*BUFW*4);
        uint32_t bAl = bAh + TILEW*4;
        uint32_t bBh = bAl + TILEW*4;
        uint32_t bBl = bBh + TILEW*4;

        #pragma unroll
        for (int ks = 0; ks < 2; ks++) {        // two k16 steps per chunk
            uint32_t ks32 = (uint32_t)(ks*32);
            uint32_t ah[2][4], al[2][4], bh[4][4], bl[4][4];
            #pragma unroll
            for (int i = 0; i < 2; i++) {
                ldsm4(ah[i], bAh + aoff[i] + ks32);
                ldsm4(al[i], bAl + aoff[i] + ks32);
            }
            #pragma unroll
            for (int g = 0; g < 4; g++) {
                ldsm4(bh[g], bBh + boff[g] + ks32);
                ldsm4(bl[g], bBl + boff[g] + ks32);
            }
            #pragma unroll
            for (int i = 0; i < 2; i++)
                #pragma unroll
                for (int j = 0; j < 8; j++) {
                    int g = j >> 1, o = (j & 1)*2;
                    mma_bf16(acc[i][j], ah[i][0], ah[i][1], ah[i][2], ah[i][3], bh[g][o], bh[g][o+1]);
                    mma_bf16(acc[i][j], ah[i][0], ah[i][1], ah[i][2], ah[i][3], bl[g][o], bl[g][o+1]);
                    mma_bf16(acc[i][j], al[i][0], al[i][1], al[i][2], al[i][3], bh[g][o], bh[g][o+1]);
                }
        }
        if (t + 1 < ntiles) store_tiles(buf ^ 1);
        __syncthreads();
    }

    // epilogue: c fragment (tq row group, tr k-pair -> cols tr*2, tr*2+1)
    int etq = lane >> 2, etr = lane & 3;
    #pragma unroll
    for (int i = 0; i < 2; i++) {
        #pragma unroll
        for (int half8 = 0; half8 < 2; half8++) {   // c0,c1 (row tq) / c2,c3 (row tq+8)
            int gm = bm + wm*32 + i*16 + half8*8 + etq;
            if (gm < mrows) {
                int orow = sca ? sca[gm] : gm;
                #pragma unroll
                for (int j = 0; j < 8; j++) {
                    int col = bn + wn*64 + j*8 + etr*2;
                    float vx = acc[i][j][half8*2 + 0];
                    float vy = acc[i][j][half8*2 + 1];
                    float* cp = C + (size_t)orow*N + col;
                    if (EPI == 1) {
                        vx = vx/(1.f + __expf(-vx)); vy = vy/(1.f + __expf(-vy));
                    } else if (EPI == 2) {
                        vx = 1.f/(1.f + __expf(-vx)); vy = 1.f/(1.f + __expf(-vy));
                    } else if (EPI == 3) {
                        const float* rp = Res + (size_t)gm*N + col;
                        vx += rp[0]; vy += rp[1];
                    } else if (EPI == 5) {
                        vx *= cp[0]; vy *= cp[1];
                    }
                    cp[0] = vx; cp[1] = vy;
                }
            }
        }
    }
}

// ---------------- rmsnorm ----------------
__global__ void rmsnorm_kernel(const float* __restrict__ in, const float* __restrict__ w,
                               float* __restrict__ out, float eps)
{
    int n = blockIdx.x; int tid = threadIdx.x;
    const float* row = in + (size_t)n*HID;
    float s = 0.f;
    for (int c = tid; c < HID; c += 256) { float v = row[c]; s += v*v; }
    __shared__ float red[256];
    red[tid] = s; __syncthreads();
    for (int o = 128; o > 0; o >>= 1) { if (tid < o) red[tid] += red[tid+o]; __syncthreads(); }
    float inv = rsqrtf(red[0]/(float)HID + eps);
    float* orow = out + (size_t)n*HID;
    for (int c = tid; c < HID; c += 256) orow[c] = row[c]*inv*w[c];
}

__global__ void rmsnorm_gate_kernel(const float* __restrict__ in, const float* __restrict__ w,
                                    const float* __restrict__ gate, float* __restrict__ out)
{
    int n = blockIdx.x; int tid = threadIdx.x;
    const float* row = in + (size_t)n*HID;
    float s = 0.f;
    for (int c = tid; c < HID; c += 256) { float v = row[c]; s += v*v; }
    __shared__ float red[256];
    red[tid] = s; __syncthreads();
    for (int o = 128; o > 0; o >>= 1) { if (tid < o) red[tid] += red[tid+o]; __syncthreads(); }
    float inv = rsqrtf(red[0]/(float)HID + 1.1920929e-07f);
    const float* grow = gate + (size_t)n*HID;
    float* orow = out + (size_t)n*HID;
    for (int c = tid; c < HID; c += 256) orow[c] = row[c]*inv*w[c]*grow[c];
}

// ---------------- router + routing ----------------
__global__ void zero_cnt_kernel(int* cnt) { if (threadIdx.x < NEXP) cnt[threadIdx.x] = 0; }

__global__ void router_kernel(const float* __restrict__ h2, const float* __restrict__ rw,
                              float* __restrict__ slotw, int* __restrict__ btok,
                              int* __restrict__ bdst, int* __restrict__ cnt)
{
    int n = blockIdx.x; int tid = threadIdx.x;
    int e = tid >> 5, lane = tid & 31;
    const float* xr = h2 + (size_t)n*HID;
    const float* wr = rw + (size_t)e*HID;
    float s = 0.f;
    for (int k = lane; k < HID; k += 32) s += xr[k]*wr[k];
    for (int o = 16; o > 0; o >>= 1) s += __shfl_down_sync(0xffffffffu, s, o);
    __shared__ float lg[NEXP];
    if (lane == 0) lg[e] = s;
    __syncthreads();
    if (tid == 0) {
        float m = lg[0];
        for (int i = 1; i < NEXP; i++) m = fmaxf(m, lg[i]);
        float p[NEXP];
        for (int i = 0; i < NEXP; i++) p[i] = expf(lg[i]-m);
        int i0 = 0;
        for (int i = 1; i < NEXP; i++) if (p[i] > p[i0]) i0 = i;
        int i1 = (i0 == 0) ? 1 : 0;
        for (int i = 0; i < NEXP; i++) if (i != i0 && p[i] > p[i1]) i1 = i;
        float inv = 1.f/(p[i0]+p[i1]);
        slotw[n*2]   = p[i0]*inv;
        slotw[n*2+1] = p[i1]*inv;
        int pos0 = atomicAdd(&cnt[i0], 1); btok[i0*NTOK+pos0] = n; bdst[i0*NTOK+pos0] = n*2;
        int pos1 = atomicAdd(&cnt[i1], 1); btok[i1*NTOK+pos1] = n; bdst[i1*NTOK+pos1] = n*2+1;
    }
}

// ---------------- attention: per-block KV contribution (2 row-half partials) --
__global__ void __launch_bounds__(256) kv_contrib_kernel(const float* __restrict__ slope)
{
    int blk = blockIdx.x, h = blockIdx.y, part = blockIdx.z;
    float sl = slope[h];
    __shared__ float Ks[32][132];
    __shared__ float Vs[32][132];
    int tid = threadIdx.x, ty = tid >> 4, tx = tid & 15;
    int lrow = tid >> 3, cb = tid & 7;

    float acc[8][8];
    #pragma unroll
    for (int i = 0; i < 8; i++)
        #pragma unroll
        for (int j = 0; j < 8; j++) acc[i][j] = 0.f;

    for (int i0 = 0; i0 < 128; i0 += 32) {
        int rowin = part*128 + i0 + lrow;
        int gi = blk*BLK + rowin;
        float kd = __expf(-sl*(float)(BLK - (rowin + 1)));
        const float* kp = g_qkv + (size_t)gi*QKVD + h*384 + 128;
        #pragma unroll
        for (int j = 0; j < 4; j++) {
            int c = (cb + j*8)*4;
            float4 kv = *(const float4*)(kp + c);
            Ks[lrow][c+0] = kv.x*kd; Ks[lrow][c+1] = kv.y*kd;
            Ks[lrow][c+2] = kv.z*kd; Ks[lrow][c+3] = kv.w*kd;
            float4 vv = *(const float4*)(kp + 128 + c);
            *(float4*)&Vs[lrow][c] = vv;
        }
        __syncthreads();
        #pragma unroll
        for (int i = 0; i < 32; i++) {
            float4 a0 = *(const float4*)&Ks[i][ty*8];
            float4 a1 = *(const float4*)&Ks[i][ty*8+4];
            float4 b0 = *(const float4*)&Vs[i][tx*8];
            float4 b1 = *(const float4*)&Vs[i][tx*8+4];
            float a[8] = {a0.x,a0.y,a0.z,a0.w,a1.x,a1.y,a1.z,a1.w};
            float b[8] = {b0.x,b0.y,b0.z,b0.w,b1.x,b1.y,b1.z,b1.w};
            #pragma unroll
            for (int rr = 0; rr < 8; rr++)
                #pragma unroll
                for (int cc = 0; cc < 8; cc++) acc[rr][cc] += a[rr]*b[cc];
        }
        __syncthreads();
    }
    float* cp = g_kvC + (size_t)((part*NH + h)*NBLK + blk)*HD*HD;
    #pragma unroll
    for (int rr = 0; rr < 8; rr++)
        #pragma unroll
        for (int cc = 0; cc < 8; cc++)
            cp[(size_t)(ty*8+rr)*HD + tx*8 + cc] = acc[rr][cc];
}

// kv_in(i) = sum_{j<i} bdecay^{i-1-j} (C0_j + C1_j)  -- x-plane split 4 ways
__global__ void kv_prefix_kernel(const float* __restrict__ slope)
{
    int i = blockIdx.x, h = blockIdx.y, zs = blockIdx.z, tid = threadIdx.x;
    float bd = __expf(-slope[h]*(float)BLK);
    const float* b0 = g_kvC + (size_t)(h*NBLK)*HD*HD;
    const float* b1 = g_kvC + (size_t)((NH + h)*NBLK)*HD*HD;
    float* outp = g_kvin + (size_t)(h*NBLK + i)*HD*HD;
    int x0 = zs*(HD*HD/4);
    for (int x = x0 + tid; x < x0 + HD*HD/4; x += 256) {
        float s = 0.f, w = 1.f;
        for (int j = i-1; j >= 0; j--) {
            float cj = b0[(size_t)j*HD*HD + x] + b1[(size_t)j*HD*HD + x];
            s += w*cj; w *= bd;
        }
        outp[x] = s;
    }
}

#define ATTN_SMEM ((128*132 + 128*36 + 32*132 + 32*132)*4)
__global__ void __launch_bounds__(256) attn_out_kernel(const float* __restrict__ slope)
{
    int m0 = blockIdx.x*128;
    int blk = blockIdx.y;
    int h = blockIdx.z;
    float sl = slope[h];

    extern __shared__ float sm[];
    float* QsT = sm;
    float* KsT = QsT + 128*132;
    float* Vs  = KsT + 128*36;
    float* ScT = Vs  + 32*132;

    int tid = threadIdx.x, ty = tid >> 4, tx = tid & 15;

    {
        int m = tid >> 1, half = tid & 1;
        const float* qp = g_qkv + (size_t)(blk*BLK + m0 + m)*QKVD + h*384;
        #pragma unroll
        for (int j = 0; j < 16; j++) {
            int d = (half*16 + j)*4;
            float4 q = *(const float4*)(qp + d);
            QsT[(d+0)*132 + m] = q.x; QsT[(d+1)*132 + m] = q.y;
            QsT[(d+2)*132 + m] = q.z; QsT[(d+3)*132 + m] = q.w;
        }
    }
    float qd[8];
    #pragma unroll
    for (int i = 0; i < 8; i++) qd[i] = __expf(-sl*(float)(m0 + ty*8 + i + 1));

    float acc[8][8];
    #pragma unroll
    for (int i = 0; i < 8; i++)
        #pragma unroll
        for (int j = 0; j < 8; j++) acc[i][j] = 0.f;
    __syncthreads();

    int lrow = tid >> 3, cb = tid & 7;

    const float* kvp = g_kvin + (size_t)(h*NBLK + blk)*HD*HD;
    for (int dc = 0; dc < 4; dc++) {
        #pragma unroll
        for (int j = 0; j < 4; j++) {
            int c = (cb + j*8)*4;
            float4 v = *(const float4*)(kvp + (size_t)(dc*32 + lrow)*HD + c);
            *(float4*)&Vs[lrow*132 + c] = v;
        }
        __syncthreads();
        #pragma unroll
        for (int i = 0; i < 32; i++) {
            int d = dc*32 + i;
            float4 a0 = *(const float4*)&QsT[d*132 + ty*8];
            float4 a1 = *(const float4*)&QsT[d*132 + ty*8 + 4];
            float4 b0 = *(const float4*)&Vs[i*132 + tx*8];
            float4 b1 = *(const float4*)&Vs[i*132 + tx*8 + 4];
            float a[8] = {a0.x,a0.y,a0.z,a0.w,a1.x,a1.y,a1.z,a1.w};
            float b[8] = {b0.x,b0.y,b0.z,b0.w,b1.x,b1.y,b1.z,b1.w};
            #pragma unroll
            for (int rr = 0; rr < 8; rr++) {
                float av = a[rr]*qd[rr];
                #pragma unroll
                for (int cc = 0; cc < 8; cc++) acc[rr][cc] += av*b[cc];
            }
        }
        __syncthreads();
    }

    int ncmax = (m0 + 128)/32;
    for (int nc = 0; nc < ncmax; nc++) {
        int n0 = nc*32;
        const float* kp = g_qkv + (size_t)(blk*BLK + n0 + lrow)*QKVD + h*384 + 128;
        #pragma unroll
        for (int j = 0; j < 4; j++) {
            int d = (cb + j*8)*4;
            float4 kv = *(const float4*)(kp + d);
            KsT[(d+0)*36 + lrow] = kv.x; KsT[(d+1)*36 + lrow] = kv.y;
            KsT[(d+2)*36 + lrow] = kv.z; KsT[(d+3)*36 + lrow] = kv.w;
            float4 vv = *(const float4*)(kp + 128 + d);
            *(float4*)&Vs[lrow*132 + d] = vv;
        }
        __syncthreads();

        float s[8][2];
        #pragma unroll
        for (int rr = 0; rr < 8; rr++) { s[rr][0] = 0.f; s[rr][1] = 0.f; }
        for (int d = 0; d < 128; d++) {
            float4 a0 = *(const float4*)&QsT[d*132 + ty*8];
            float4 a1 = *(const float4*)&QsT[d*132 + ty*8 + 4];
            float b0 = KsT[d*36 + tx*2], b1 = KsT[d*36 + tx*2 + 1];
            float a[8] = {a0.x,a0.y,a0.z,a0.w,a1.x,a1.y,a1.z,a1.w};
            #pragma unroll
            for (int rr = 0; rr < 8; rr++) { s[rr][0] += a[rr]*b0; s[rr][1] += a[rr]*b1; }
        }
        #pragma unroll
        for (int rr = 0; rr < 8; rr++) {
            int mg = m0 + ty*8 + rr;
            #pragma unroll
            for (int j = 0; j < 2; j++) {
                int ng = n0 + tx*2 + j;
                float v = (mg >= ng) ? s[rr][j]*__expf(-sl*(float)(mg-ng)) : 0.f;
                ScT[(tx*2 + j)*132 + ty*8 + rr] = v;
            }
        }
        __syncthreads();
        #pragma unroll
        for (int n = 0; n < 32; n++) {
            float4 a0 = *(const float4*)&ScT[n*132 + ty*8];
            float4 a1 = *(const float4*)&ScT[n*132 + ty*8 + 4];
            float4 b0 = *(const float4*)&Vs[n*132 + tx*8];
            float4 b1 = *(const float4*)&Vs[n*132 + tx*8 + 4];
            float a[8] = {a0.x,a0.y,a0.z,a0.w,a1.x,a1.y,a1.z,a1.w};
            float b[8] = {b0.x,b0.y,b0.z,b0.w,b1.x,b1.y,b1.z,b1.w};
            #pragma unroll
            for (int rr = 0; rr < 8; rr++)
                #pragma unroll
                for (int cc = 0; cc < 8; cc++) acc[rr][cc] += a[rr]*b[cc];
        }
        __syncthreads();
    }

    #pragma unroll
    for (int rr = 0; rr < 8; rr++) {
        float* op = g_attn + (size_t)(blk*BLK + m0 + ty*8 + rr)*HID + h*HD + tx*8;
        #pragma unroll
        for (int cc = 0; cc < 8; cc++) op[cc] = acc[rr][cc];
    }
}

// ---------------- final combine ----------------
__global__ void combine_kernel(const float* __restrict__ hid2, const float* __restrict__ yslot,
                               const float* __restrict__ sw, float* __restrict__ out)
{
    int idx = blockIdx.x*256 + threadIdx.x;
    int n = idx / HID; int c = idx % HID;
    out[idx] = hid2[idx]
             + sw[n*2]   * yslot[(size_t)(n*2)  *HID + c]
             + sw[n*2+1] * yslot[(size_t)(n*2+1)*HID + c];
}

// ---------------- launch ----------------
extern "C" void kernel_launch(void* const* d_in, const int* in_sizes, int n_in,
                              void* d_out, int out_size)
{
    (void)in_sizes; (void)n_in; (void)out_size;
    const float* x     = (const float*)d_in[0];
    const float* slope = (const float*)d_in[1];
    const float* ln1   = (const float*)d_in[2];
    const float* ln2   = (const float*)d_in[3];
    const float* qkvw  = (const float*)d_in[4];
    const float* ogw   = (const float*)d_in[5];
    const float* anw   = (const float*)d_in[6];
    const float* aow   = (const float*)d_in[7];
    const float* rw    = (const float*)d_in[8];
    const float* w1    = (const float*)d_in[9];
    const float* w2    = (const float*)d_in[10];
    const float* w3    = (const float*)d_in[11];
    float* out = (float*)d_out;

    float *p_h, *p_qkv, *p_gate, *p_attn, *p_attnng, *p_hid2, *p_h2, *p_act, *p_yslot, *p_slotw;
    int *p_btok, *p_bdst, *p_cnt;
    cudaGetSymbolAddress((void**)&p_h, g_h);
    cudaGetSymbolAddress((void**)&p_qkv, g_qkv);
    cudaGetSymbolAddress((void**)&p_gate, g_gate);
    cudaGetSymbolAddress((void**)&p_attn, g_attn);
    cudaGetSymbolAddress((void**)&p_attnng, g_attnng);
    cudaGetSymbolAddress((void**)&p_hid2, g_hid2);
    cudaGetSymbolAddress((void**)&p_h2, g_h2);
    cudaGetSymbolAddress((void**)&p_act, g_act);
    cudaGetSymbolAddress((void**)&p_yslot, g_yslot);
    cudaGetSymbolAddress((void**)&p_slotw, g_slotw);
    cudaGetSymbolAddress((void**)&p_btok, g_btok);
    cudaGetSymbolAddress((void**)&p_bdst, g_bdst);
    cudaGetSymbolAddress((void**)&p_cnt, g_cnt);

    cudaFuncSetAttribute(attn_out_kernel, cudaFuncAttributeMaxDynamicSharedMemorySize, ATTN_SMEM);
    cudaFuncSetAttribute(bgemm_kernel<0>, cudaFuncAttributeMaxDynamicSharedMemorySize, BG_SMEM);
    cudaFuncSetAttribute(bgemm_kernel<1>, cudaFuncAttributeMaxDynamicSharedMemorySize, BG_SMEM);
    cudaFuncSetAttribute(bgemm_kernel<2>, cudaFuncAttributeMaxDynamicSharedMemorySize, BG_SMEM);
    cudaFuncSetAttribute(bgemm_kernel<3>, cudaFuncAttributeMaxDynamicSharedMemorySize, BG_SMEM);
    cudaFuncSetAttribute(bgemm_kernel<5>, cudaFuncAttributeMaxDynamicSharedMemorySize, BG_SMEM);

    // 1. rmsnorm1
    rmsnorm_kernel<<<NTOK, 256>>>(x, ln1, p_h, 1e-5f);
    // 2. qkv = silu(h @ qkv_w^T)
    bgemm_kernel<1><<<dim3(QKVD/128, NTOK/128, 1), 256, BG_SMEM>>>(
        p_h, qkvw, 0, nullptr, p_qkv, NTOK, QKVD, HID, nullptr, nullptr, nullptr);
    // 3. gate = sigmoid(h @ ogate_w^T)
    bgemm_kernel<2><<<dim3(HID/128, NTOK/128, 1), 256, BG_SMEM>>>(
        p_h, ogw, 0, nullptr, p_gate, NTOK, HID, HID, nullptr, nullptr, nullptr);
    // 4-6. lightning attention (kv split into 2 row-half partials; prefix 4-way)
    kv_contrib_kernel<<<dim3(NBLK, NH, 2), 256>>>(slope);
    kv_prefix_kernel<<<dim3(NBLK, NH, 4), 256>>>(slope);
    attn_out_kernel<<<dim3(2, NBLK, NH), 256, ATTN_SMEM>>>(slope);
    // 7. rmsnorm(attn)*gate
    rmsnorm_gate_kernel<<<NTOK, 256>>>(p_attn, anw, p_gate, p_attnng);
    // 8. hid2 = x + attnng @ aout_w^T
    bgemm_kernel<3><<<dim3(HID/128, NTOK/128, 1), 256, BG_SMEM>>>(
        p_attnng, aow, 0, x, p_hid2, NTOK, HID, HID, nullptr, nullptr, nullptr);
    // 9. rmsnorm2
    rmsnorm_kernel<<<NTOK, 256>>>(p_hid2, ln2, p_h2, 1e-5f);
    // 10-11. routing
    zero_cnt_kernel<<<1, 32>>>(p_cnt);
    router_kernel<<<NTOK, 256>>>(p_h2, rw, p_slotw, p_btok, p_bdst, p_cnt);
    // 12. batched MoE on tensor cores (R11 three-stage structure)
    bgemm_kernel<1><<<dim3(FFN/128, NTOK/128, NEXP), 256, BG_SMEM>>>(
        p_h2, w1, (size_t)FFN*HID, nullptr, p_act, NTOK, FFN, HID, p_btok, p_bdst, p_cnt);
    bgemm_kernel<5><<<dim3(FFN/128, NTOK/128, NEXP), 256, BG_SMEM>>>(
        p_h2, w3, (size_t)FFN*HID, nullptr, p_act, NTOK, FFN, HID, p_btok, p_bdst, p_cnt);
    bgemm_kernel<0><<<dim3(HID/128, NTOK/128, NEXP), 256, BG_SMEM>>>(
        p_act, w2, (size_t)HID*FFN, nullptr, p_yslot, NTOK, HID, FFN, p_bdst, p_bdst, p_cnt);
    // 13. out = hid2 + sum_k w_k * y_k
    combine_kernel<<<NTOK*HID/256, 256>>>(p_hid2, p_yslot, p_slotw, out);
}